// round 10
// baseline (speedup 1.0000x reference)
#include <cuda_runtime.h>
#include <cuda_bf16.h>
#include <math.h>
#include <stdint.h>

// Problem constants
#define B  32768
#define K  8192
#define D  1024
#define DECAY   0.99f
#define ONE_M_D 0.01f
#define EPS     1e-5f
#define COMMIT  0.25f
#define NORM_EPS 1e-12f

// Candidate machinery
#define CAP    64
#define MARGIN 0.15f

// Output layout (flattened tuple, float32)
#define OFF_ZQ   0
#define OFF_IDS  (B*D)
#define OFF_LOSS (OFF_IDS + B)
#define OFF_CB   (OFF_LOSS + 1)              // odd -> no float4 stores
#define OFF_CNT  (OFF_CB + K*D)
#define OFF_W    (OFF_CNT + K)               // odd -> no float4 stores

// -------------------- device scratch (no allocation allowed) ----------------
__device__ __align__(16) int8_t g_qa[(size_t)B * D];   // int8 quantized z
__device__ __align__(16) int8_t g_qb[(size_t)K * D];   // int8 quantized cb_norm
__device__ float g_sz[B];                              // z row scale
__device__ float g_sc[K];                              // cb row scale
__device__ __align__(16) float g_cbn[(size_t)K * D];   // fp32 cb_norm (rescore)
__device__ __align__(16) float g_wsum[K * D];
__device__ int   g_cand[(size_t)B * CAP];
__device__ int   g_ccnt[B];
__device__ float g_cnt[K];
__device__ float g_ncnt[K];
__device__ int   g_ids[B];
__device__ float g_loss;

// -------------------- PTX helpers (compute_103-safe) ------------------------
__device__ __forceinline__ uint32_t smem_u32(const void* p) {
    uint32_t a;
    asm("{ .reg .u64 t; cvta.to.shared.u64 t, %1; cvt.u32.u64 %0, t; }"
        : "=r"(a) : "l"(p));
    return a;
}
__device__ __forceinline__ void cp_async16(uint32_t dst, const void* src) {
    asm volatile("cp.async.cg.shared.global [%0], [%1], 16;"
                 :: "r"(dst), "l"(src) : "memory");
}
__device__ __forceinline__ void cp_commit() {
    asm volatile("cp.async.commit_group;" ::: "memory");
}
template <int N> __device__ __forceinline__ void cp_wait() {
    asm volatile("cp.async.wait_group %0;" :: "n"(N) : "memory");
}
__device__ __forceinline__ void ldsm4(uint32_t& r0, uint32_t& r1,
                                      uint32_t& r2, uint32_t& r3, uint32_t a) {
    asm volatile("ldmatrix.sync.aligned.m8n8.x4.shared.b16 {%0,%1,%2,%3}, [%4];"
                 : "=r"(r0), "=r"(r1), "=r"(r2), "=r"(r3) : "r"(a));
}
// int8 MMA: m16n8k32, s32 accumulate (exact integer dot)
__device__ __forceinline__ void mma16832(int* c, const uint32_t* a,
                                         const uint32_t* b) {
    asm volatile(
        "mma.sync.aligned.m16n8k32.row.col.s32.s8.s8.s32 "
        "{%0,%1,%2,%3}, {%4,%5,%6,%7}, {%8,%9}, {%0,%1,%2,%3};"
        : "+r"(c[0]), "+r"(c[1]), "+r"(c[2]), "+r"(c[3])
        : "r"(a[0]), "r"(a[1]), "r"(a[2]), "r"(a[3]), "r"(b[0]), "r"(b[1]));
}
#define SW128(x) ((x) ^ (((x) >> 3) & 0x70))

// order-preserving float<->uint for atomicMax
__device__ __forceinline__ unsigned fenc(float f) {
    unsigned u = __float_as_uint(f);
    return (u & 0x80000000u) ? ~u : (u | 0x80000000u);
}
__device__ __forceinline__ float fdec(unsigned u) {
    return (u & 0x80000000u) ? __uint_as_float(u ^ 0x80000000u)
                             : __uint_as_float(~u);
}

// -------------------- setup kernels -----------------------------------------
__global__ void k_zero() {
    int64_t tid = (int64_t)blockIdx.x * blockDim.x + threadIdx.x;
    int64_t stride = (int64_t)gridDim.x * blockDim.x;
    for (int64_t i = tid; i < (int64_t)K * D; i += stride) g_wsum[i] = 0.0f;
    for (int64_t i = tid; i < K; i += stride) g_cnt[i] = 0.0f;
    for (int64_t i = tid; i < B; i += stride) g_ccnt[i] = 0;
    if (tid == 0) g_loss = 0.0f;
}

// quantize z rows to int8 with per-row scale. one block per row.
__global__ void k_quant_z(const float* __restrict__ z) {
    __shared__ float red[256];
    int b = blockIdx.x;
    int t = threadIdx.x;
    float4 v = ((const float4*)(z + (size_t)b * D))[t];
    float ma = fmaxf(fmaxf(fabsf(v.x), fabsf(v.y)),
                     fmaxf(fabsf(v.z), fabsf(v.w)));
    red[t] = ma;
    __syncthreads();
    for (int s = 128; s > 0; s >>= 1) {
        if (t < s) red[t] = fmaxf(red[t], red[t + s]);
        __syncthreads();
    }
    float mx = fmaxf(red[0], 1e-20f);
    float inv = 127.0f / mx;
    char4 q;
    q.x = (signed char)__float2int_rn(v.x * inv);
    q.y = (signed char)__float2int_rn(v.y * inv);
    q.z = (signed char)__float2int_rn(v.z * inv);
    q.w = (signed char)__float2int_rn(v.w * inv);
    ((char4*)(g_qa + (size_t)b * D))[t] = q;
    if (t == 0) g_sz[b] = mx / 127.0f;
}

// normalize codebook rows -> fp32 g_cbn + int8 g_qb + scale. one block per row.
__global__ void k_norm_cb(const float* __restrict__ cb) {
    __shared__ float red[256];
    int k = blockIdx.x;
    int t = threadIdx.x;
    float4 v = ((const float4*)(cb + (size_t)k * D))[t];
    red[t] = v.x * v.x + v.y * v.y + v.z * v.z + v.w * v.w;
    __syncthreads();
    for (int s = 128; s > 0; s >>= 1) {
        if (t < s) red[t] += red[t + s];
        __syncthreads();
    }
    float denom = fmaxf(sqrtf(red[0]), NORM_EPS);
    __syncthreads();
    float ma = fmaxf(fmaxf(fabsf(v.x), fabsf(v.y)),
                     fmaxf(fabsf(v.z), fabsf(v.w)));
    red[t] = ma;
    __syncthreads();
    for (int s = 128; s > 0; s >>= 1) {
        if (t < s) red[t] = fmaxf(red[t], red[t + s]);
        __syncthreads();
    }
    float mx = fmaxf(red[0], 1e-30f);

    float4 o;
    o.x = v.x / denom; o.y = v.y / denom; o.z = v.z / denom; o.w = v.w / denom;
    ((float4*)(g_cbn + (size_t)k * D))[t] = o;

    float inv = 127.0f / mx;                 // quantize o*denom = v directly
    char4 q;
    q.x = (signed char)__float2int_rn(v.x * inv);
    q.y = (signed char)__float2int_rn(v.y * inv);
    q.z = (signed char)__float2int_rn(v.z * inv);
    q.w = (signed char)__float2int_rn(v.w * inv);
    ((char4*)(g_qb + (size_t)k * D))[t] = q;
    if (t == 0) g_sc[k] = mx / (127.0f * denom);
}

// -------------------- int8 approx GEMM + candidate harvest ------------------
// CTA: 128 rows, sweeps 64 N-tiles of 128. 8 warps = 4(M) x 2(N), warp 32x64.
// Chunk = 128 k-int8 (128B rows) -> NDK=8. 3-stage cp.async pipeline.
// approx sim = s_z[row] * s_c[col] * idot  (idot exact int32).
#define DKC   128
#define NDK   (D / DKC)               // 8
#define NT    (K / 128)               // 64
#define NCHUNK (NT * NDK)             // 512
#define TILE_B 16384                  // 128 rows x 128 bytes
#define STAGE_B (2 * TILE_B)          // 32 KB
#define STAGES 3
#define DYN_SMEM (STAGES * STAGE_B)   // 96 KB

__device__ __forceinline__ void load_chunk(uint32_t sbase, int t, int tid,
                                           const int8_t* asrc0) {
    int nt = t >> 3;
    int dk = t & 7;
    uint32_t sb = sbase + (t % STAGES) * STAGE_B;
    int koff = dk * DKC;
    const int8_t* srcs[2] = {
        asrc0 + koff,
        g_qb + (size_t)nt * 128 * D + koff };
#pragma unroll
    for (int t2 = 0; t2 < 2; t2++) {
        const int8_t* src = srcs[t2];
#pragma unroll
        for (int it = 0; it < 4; it++) {
            int c = tid + 256 * it;
            int r = c >> 3, ch = c & 7;
            cp_async16(sb + t2 * TILE_B + SW128(r * 128 + ch * 16),
                       src + (size_t)r * D + ch * 16);
        }
    }
    cp_commit();
}

__global__ __launch_bounds__(256, 2)
void k_approx(int dummy) {
    extern __shared__ char dyn[];
    __shared__ unsigned srowmax[128];
    __shared__ float s_rmv[128];      // MARGIN / s_z  per local row
    __shared__ float s_scb[128];      // s_c for current tile's 128 cols
    uint32_t sbase = smem_u32(dyn);

    int tid = threadIdx.x;
    int lane = tid & 31;
    int wid = tid >> 5;
    int warp_m = wid >> 1;            // 0..3
    int warp_n = wid & 1;             // 0..1
    int g = lane >> 2;                // 0..7
    int tig = lane & 3;               // 0..3
    int row0 = blockIdx.x * 128;

    int lm_r = lane & 15;
    int lm_c = (lane >> 4) << 4;

    if (tid < 128) {
        srowmax[tid] = 0u;            // < fenc of any float
        s_rmv[tid] = MARGIN / g_sz[row0 + tid];
    }
    __syncthreads();

    const int8_t* asrc0 = g_qa + (size_t)row0 * D;

    // prologue: chunks 0,1
    load_chunk(sbase, 0, tid, asrc0);
    load_chunk(sbase, 1, tid, asrc0);

    for (int nt = 0; nt < NT; nt++) {
        if (tid < 128) s_scb[tid] = g_sc[nt * 128 + tid];

        int acc[2][8][4];
#pragma unroll
        for (int i = 0; i < 2; i++)
#pragma unroll
            for (int j = 0; j < 8; j++)
#pragma unroll
                for (int q = 0; q < 4; q++) acc[i][j][q] = 0;

        for (int dk = 0; dk < NDK; dk++) {
            int t = nt * NDK + dk;
            if (t == NCHUNK - 1) cp_wait<0>(); else cp_wait<1>();
            __syncthreads();

            uint32_t stg = sbase + (t % STAGES) * STAGE_B;
#pragma unroll
            for (int step = 0; step < 4; step++) {
                int kc = step * 32 + lm_c;
                uint32_t afr[2][4];
#pragma unroll
                for (int mi = 0; mi < 2; mi++) {
                    int r = warp_m * 32 + mi * 16 + lm_r;
                    uint32_t addr = stg + SW128(r * 128 + kc);
                    ldsm4(afr[mi][0], afr[mi][1], afr[mi][2], afr[mi][3], addr);
                }
                uint32_t bfr[4][4];
#pragma unroll
                for (int nb = 0; nb < 4; nb++) {
                    int r = warp_n * 64 + nb * 16 + lm_r;
                    uint32_t addr = stg + TILE_B + SW128(r * 128 + kc);
                    ldsm4(bfr[nb][0], bfr[nb][1], bfr[nb][2], bfr[nb][3], addr);
                }
#pragma unroll
                for (int mi = 0; mi < 2; mi++) {
#pragma unroll
                    for (int nb = 0; nb < 4; nb++) {
                        uint32_t b0[2] = { bfr[nb][0], bfr[nb][2] };
                        uint32_t b1[2] = { bfr[nb][1], bfr[nb][3] };
                        mma16832(acc[mi][nb * 2 + 0], afr[mi], b0);
                        mma16832(acc[mi][nb * 2 + 1], afr[mi], b1);
                    }
                }
            }
            if (t + 2 < NCHUNK) load_chunk(sbase, t + 2, tid, asrc0);
        }

        // ---- epilogue: v = s_c[col] * idot; running rowmax; insert
#pragma unroll
        for (int i = 0; i < 2; i++) {
#pragma unroll
            for (int kk = 0; kk < 2; kk++) {
                int lrow = warp_m * 32 + i * 16 + kk * 8 + g;
                float m = -INFINITY;
#pragma unroll
                for (int j = 0; j < 8; j++) {
#pragma unroll
                    for (int h = 0; h < 2; h++) {
                        float v = s_scb[warp_n * 64 + j * 8 + tig * 2 + h] *
                                  (float)acc[i][j][kk * 2 + h];
                        m = fmaxf(m, v);
                    }
                }
                atomicMax(&srowmax[lrow], fenc(m));
            }
        }
        __syncthreads();
#pragma unroll
        for (int i = 0; i < 2; i++) {
#pragma unroll
            for (int kk = 0; kk < 2; kk++) {
                int lrow = warp_m * 32 + i * 16 + kk * 8 + g;
                float thr = fdec(srowmax[lrow]) - s_rmv[lrow];
                float m = -INFINITY;
#pragma unroll
                for (int j = 0; j < 8; j++) {
#pragma unroll
                    for (int h = 0; h < 2; h++) {
                        float v = s_scb[warp_n * 64 + j * 8 + tig * 2 + h] *
                                  (float)acc[i][j][kk * 2 + h];
                        m = fmaxf(m, v);
                    }
                }
                if (m < thr) continue;
#pragma unroll
                for (int j = 0; j < 8; j++) {
#pragma unroll
                    for (int h = 0; h < 2; h++) {
                        float v = s_scb[warp_n * 64 + j * 8 + tig * 2 + h] *
                                  (float)acc[i][j][kk * 2 + h];
                        if (v >= thr) {
                            int col = nt * 128 + warp_n * 64 + j * 8 + tig * 2 + h;
                            int grow = row0 + lrow;
                            int p = atomicAdd(&g_ccnt[grow], 1);
                            if (p < CAP) g_cand[(size_t)grow * CAP + p] = col;
                        }
                    }
                }
            }
        }
        __syncthreads();   // protect s_scb before next nt overwrites it
    }
}

// -------------------- exact rescore: one warp per row -----------------------
__global__ __launch_bounds__(256)
void k_rescore(const float* __restrict__ z) {
    int row = blockIdx.x * 8 + (threadIdx.x >> 5);
    int lane = threadIdx.x & 31;
    int cnt = g_ccnt[row];
    if (cnt > CAP) cnt = CAP;

    float4 zr[8];
    const float4* zp = (const float4*)(z + (size_t)row * D);
#pragma unroll
    for (int i = 0; i < 8; i++) zr[i] = zp[i * 32 + lane];

    float bv = -INFINITY;
    int   bi = 0;
    for (int c = 0; c < cnt; c++) {
        int idx = g_cand[(size_t)row * CAP + c];
        const float4* cp = (const float4*)(g_cbn + (size_t)idx * D);
        float s = 0.0f;
#pragma unroll
        for (int i = 0; i < 8; i++) {
            float4 cv = cp[i * 32 + lane];
            s += zr[i].x * cv.x + zr[i].y * cv.y + zr[i].z * cv.z + zr[i].w * cv.w;
        }
#pragma unroll
        for (int o = 16; o > 0; o >>= 1) s += __shfl_xor_sync(0xFFFFFFFFu, s, o);
        if (s > bv || (s == bv && idx < bi)) { bv = s; bi = idx; }
    }
    if (lane == 0) g_ids[row] = bi;
}

// -------------------- epilogue kernels --------------------------------------
__global__ void k_scatter(const float* __restrict__ z,
                          const float* __restrict__ cb,
                          float* __restrict__ out) {
    __shared__ float red[256];
    int b = blockIdx.x;
    int t = threadIdx.x;
    int id = g_ids[b];

    float4 zv = ((const float4*)(z  + (size_t)b  * D))[t];
    float4 qv = ((const float4*)(cb + (size_t)id * D))[t];

    float4 zq;
    zq.x = zv.x + (qv.x - zv.x);
    zq.y = zv.y + (qv.y - zv.y);
    zq.z = zv.z + (qv.z - zv.z);
    zq.w = zv.w + (qv.w - zv.w);
    ((float4*)(out + OFF_ZQ + (size_t)b * D))[t] = zq;

    float dx = zv.x - qv.x, dy = zv.y - qv.y, dz = zv.z - qv.z, dw = zv.w - qv.w;
    red[t] = dx * dx + dy * dy + dz * dz + dw * dw;

    float* wrow = g_wsum + (size_t)id * D + t * 4;
    atomicAdd(wrow + 0, zv.x);
    atomicAdd(wrow + 1, zv.y);
    atomicAdd(wrow + 2, zv.z);
    atomicAdd(wrow + 3, zv.w);

    __syncthreads();
    for (int s = 128; s > 0; s >>= 1) {
        if (t < s) red[t] += red[t + s];
        __syncthreads();
    }
    if (t == 0) {
        atomicAdd(&g_loss, red[0]);
        atomicAdd(&g_cnt[id], 1.0f);
        out[OFF_IDS + b] = (float)id;
    }
}

__global__ void k_count(const float* __restrict__ ema_count,
                        float* __restrict__ out) {
    int k = blockIdx.x * blockDim.x + threadIdx.x;
    if (k < K) {
        float nc = DECAY * ema_count[k] + ONE_M_D * g_cnt[k];
        g_ncnt[k] = nc;
        out[OFF_CNT + k] = nc;
    }
}

__global__ void k_final(const float* __restrict__ ema_weight,
                        float* __restrict__ out) {
    int64_t i4 = (int64_t)blockIdx.x * blockDim.x + threadIdx.x;
    if (i4 >= (int64_t)K * D / 4) return;
    int row = (int)(i4 >> 8);
    float4 ew = ((const float4*)ema_weight)[i4];
    float4 ws = ((const float4*)g_wsum)[i4];
    float w0 = DECAY * ew.x + ONE_M_D * ws.x;
    float w1 = DECAY * ew.y + ONE_M_D * ws.y;
    float w2 = DECAY * ew.z + ONE_M_D * ws.z;
    float w3 = DECAY * ew.w + ONE_M_D * ws.w;
    int64_t base = i4 * 4;
    out[OFF_W + base + 0] = w0;
    out[OFF_W + base + 1] = w1;
    out[OFF_W + base + 2] = w2;
    out[OFF_W + base + 3] = w3;
    float denom = g_ncnt[row] + EPS;
    out[OFF_CB + base + 0] = w0 / denom;
    out[OFF_CB + base + 1] = w1 / denom;
    out[OFF_CB + base + 2] = w2 / denom;
    out[OFF_CB + base + 3] = w3 / denom;
}

__global__ void k_loss(float* __restrict__ out) {
    out[OFF_LOSS] = COMMIT * (g_loss / (float)((int64_t)B * D));
}

// ---------------------------------------------------------------------------
extern "C" void kernel_launch(void* const* d_in, const int* in_sizes, int n_in,
                              void* d_out, int out_size) {
    const float* z          = (const float*)d_in[0];
    const float* codebook   = (const float*)d_in[1];
    const float* ema_count  = (const float*)d_in[2];
    const float* ema_weight = (const float*)d_in[3];
    float* out = (float*)d_out;

    cudaFuncSetAttribute(k_approx, cudaFuncAttributeMaxDynamicSharedMemorySize,
                         DYN_SMEM);

    k_zero<<<2048, 256>>>();
    k_quant_z<<<B, 256>>>(z);
    k_norm_cb<<<K, 256>>>(codebook);
    k_approx<<<B / 128, 256, DYN_SMEM>>>(0);
    k_rescore<<<B / 8, 256>>>(z);
    k_scatter<<<B, 256>>>(z, codebook, out);
    k_count<<<(K + 255) / 256, 256>>>(ema_count, out);
    k_final<<<(K * D / 4 + 255) / 256, 256>>>(ema_weight, out);
    k_loss<<<1, 1>>>(out);
}

// round 11
// speedup vs baseline: 2.3116x; 2.3116x over previous
#include <cuda_runtime.h>
#include <cuda_bf16.h>
#include <math.h>
#include <stdint.h>

// Problem constants
#define B  32768
#define K  8192
#define D  1024
#define DECAY   0.99f
#define ONE_M_D 0.01f
#define EPS     1e-5f
#define COMMIT  0.25f
#define NORM_EPS 1e-12f

// Candidate machinery
#define CAP    64
#define MARGIN 0.15f

// Output layout (flattened tuple, float32)
#define OFF_ZQ   0
#define OFF_IDS  (B*D)
#define OFF_LOSS (OFF_IDS + B)
#define OFF_CB   (OFF_LOSS + 1)              // odd -> no float4 stores
#define OFF_CNT  (OFF_CB + K*D)
#define OFF_W    (OFF_CNT + K)               // odd -> no float4 stores

// -------------------- device scratch (no allocation allowed) ----------------
__device__ __align__(16) __nv_bfloat16 g_a0[(size_t)B * D];   // bf16(z)
__device__ __align__(16) __nv_bfloat16 g_b0[(size_t)K * D];   // bf16(cb_norm)
__device__ __align__(16) float g_cbn[(size_t)K * D];          // fp32 cb_norm
__device__ __align__(16) float g_wsum[K * D];
__device__ int   g_cand[(size_t)B * CAP];
__device__ int   g_ccnt[B];
__device__ float g_cnt[K];
__device__ float g_ncnt[K];
__device__ float g_loss;

// -------------------- PTX helpers (compute_103-safe) ------------------------
__device__ __forceinline__ uint32_t smem_u32(const void* p) {
    uint32_t a;
    asm("{ .reg .u64 t; cvta.to.shared.u64 t, %1; cvt.u32.u64 %0, t; }"
        : "=r"(a) : "l"(p));
    return a;
}
__device__ __forceinline__ void cp_async16(uint32_t dst, const void* src) {
    asm volatile("cp.async.cg.shared.global [%0], [%1], 16;"
                 :: "r"(dst), "l"(src) : "memory");
}
__device__ __forceinline__ void cp_commit() {
    asm volatile("cp.async.commit_group;" ::: "memory");
}
template <int N> __device__ __forceinline__ void cp_wait() {
    asm volatile("cp.async.wait_group %0;" :: "n"(N) : "memory");
}
__device__ __forceinline__ void ldsm4(uint32_t& r0, uint32_t& r1,
                                      uint32_t& r2, uint32_t& r3, uint32_t a) {
    asm volatile("ldmatrix.sync.aligned.m8n8.x4.shared.b16 {%0,%1,%2,%3}, [%4];"
                 : "=r"(r0), "=r"(r1), "=r"(r2), "=r"(r3) : "r"(a));
}
__device__ __forceinline__ void mma16816(float* c, const uint32_t* a,
                                         const uint32_t* b) {
    asm volatile(
        "mma.sync.aligned.m16n8k16.row.col.f32.bf16.bf16.f32 "
        "{%0,%1,%2,%3}, {%4,%5,%6,%7}, {%8,%9}, {%0,%1,%2,%3};"
        : "+f"(c[0]), "+f"(c[1]), "+f"(c[2]), "+f"(c[3])
        : "r"(a[0]), "r"(a[1]), "r"(a[2]), "r"(a[3]), "r"(b[0]), "r"(b[1]));
}
#define SW128(x) ((x) ^ (((x) >> 3) & 0x70))

// order-preserving float<->uint for atomicMax
__device__ __forceinline__ unsigned fenc(float f) {
    unsigned u = __float_as_uint(f);
    return (u & 0x80000000u) ? ~u : (u | 0x80000000u);
}
__device__ __forceinline__ float fdec(unsigned u) {
    return (u & 0x80000000u) ? __uint_as_float(u ^ 0x80000000u)
                             : __uint_as_float(~u);
}

// -------------------- setup kernels -----------------------------------------
__global__ void k_zero() {
    int64_t tid = (int64_t)blockIdx.x * blockDim.x + threadIdx.x;
    int64_t stride = (int64_t)gridDim.x * blockDim.x;
    for (int64_t i = tid; i < (int64_t)K * D; i += stride) g_wsum[i] = 0.0f;
    for (int64_t i = tid; i < K; i += stride) g_cnt[i] = 0.0f;
    for (int64_t i = tid; i < B; i += stride) g_ccnt[i] = 0;
    if (tid == 0) g_loss = 0.0f;
}

__global__ void k_cast_z(const float* __restrict__ z) {
    int64_t i = (int64_t)blockIdx.x * blockDim.x + threadIdx.x;
    int64_t n4 = (int64_t)B * D / 4;
    int64_t stride = (int64_t)gridDim.x * blockDim.x;
    for (; i < n4; i += stride) {
        float4 v = ((const float4*)z)[i];
        __nv_bfloat162* p = (__nv_bfloat162*)g_a0 + i * 2;
        __nv_bfloat162 t;
        t.x = __float2bfloat16_rn(v.x); t.y = __float2bfloat16_rn(v.y); p[0] = t;
        t.x = __float2bfloat16_rn(v.z); t.y = __float2bfloat16_rn(v.w); p[1] = t;
    }
}

// normalize codebook rows -> fp32 g_cbn + bf16 g_b0. one block per row.
__global__ void k_norm_cb(const float* __restrict__ cb) {
    __shared__ float red[256];
    int k = blockIdx.x;
    int t = threadIdx.x;
    float4 v = ((const float4*)(cb + (size_t)k * D))[t];
    red[t] = v.x * v.x + v.y * v.y + v.z * v.z + v.w * v.w;
    __syncthreads();
    for (int s = 128; s > 0; s >>= 1) {
        if (t < s) red[t] += red[t + s];
        __syncthreads();
    }
    float denom = fmaxf(sqrtf(red[0]), NORM_EPS);
    float4 o;
    o.x = v.x / denom; o.y = v.y / denom; o.z = v.z / denom; o.w = v.w / denom;
    ((float4*)(g_cbn + (size_t)k * D))[t] = o;
    __nv_bfloat162* p = (__nv_bfloat162*)g_b0 + (size_t)k * (D / 2) + t * 2;
    __nv_bfloat162 x;
    x.x = __float2bfloat16_rn(o.x); x.y = __float2bfloat16_rn(o.y); p[0] = x;
    x.x = __float2bfloat16_rn(o.z); x.y = __float2bfloat16_rn(o.w); p[1] = x;
}

// -------------------- approx bf16 GEMM + candidate harvest ------------------
// CTA: 128 rows, sweeps 64 N-tiles of 128. 8 warps = 4(M) x 2(N), warp 32x64.
// 2-stage cp.async pipeline (proven R8 structure) + double-buffered ldmatrix
// fragments: step s+1's frags load into the idle buffer while step s's MMAs
// run, breaking the WAR chain that drained the tensor pipe each step.
#define DKC   64
#define NDK   (D / DKC)               // 16
#define NT    (K / 128)               // 64
#define TILE_B 16384                  // 128 rows x 128 bytes (64 bf16 cols)
#define STAGE_B (2 * TILE_B)          // A tile + B tile = 32 KB
#define DYN_SMEM (2 * STAGE_B)        // 64 KB

__global__ __launch_bounds__(256, 2)
void k_approx(int dummy) {
    extern __shared__ char dyn[];
    __shared__ unsigned srowmax[128];
    uint32_t sbase = smem_u32(dyn);

    int tid = threadIdx.x;
    int lane = tid & 31;
    int wid = tid >> 5;
    int warp_m = wid >> 1;            // 0..3
    int warp_n = wid & 1;             // 0..1
    int g = lane >> 2;                // 0..7
    int tig = lane & 3;               // 0..3
    int row0 = blockIdx.x * 128;

    int lm_r = lane & 15;
    int lm_c = (lane >> 4) << 4;

    if (tid < 128) srowmax[tid] = 0u;   // < fenc of any float
    __syncthreads();

    const __nv_bfloat16* asrc0 = g_a0 + (size_t)row0 * D;

    for (int nt = 0; nt < NT; nt++) {
        const __nv_bfloat16* bsrc0 = g_b0 + (size_t)nt * 128 * D;

        float acc[2][8][4];
#pragma unroll
        for (int i = 0; i < 2; i++)
#pragma unroll
            for (int j = 0; j < 8; j++)
#pragma unroll
                for (int q = 0; q < 4; q++) acc[i][j][q] = 0.0f;

        // prologue: stage 0 <- dk 0 (A tile + B tile)
        {
            uint32_t sb = sbase;
#pragma unroll
            for (int t2 = 0; t2 < 2; t2++) {
                const __nv_bfloat16* src = t2 ? bsrc0 : asrc0;
#pragma unroll
                for (int it = 0; it < 4; it++) {
                    int c = tid + 256 * it;
                    int r = c >> 3, ch = c & 7;
                    cp_async16(sb + t2 * TILE_B + SW128(r * 128 + ch * 16),
                               src + (size_t)r * D + ch * 8);
                }
            }
            cp_commit();
        }

        for (int dk = 0; dk < NDK; dk++) {
            int s = dk & 1;
            if (dk + 1 < NDK) {
                uint32_t sb = sbase + (s ^ 1) * STAGE_B;
                int koff = (dk + 1) * DKC;
#pragma unroll
                for (int t2 = 0; t2 < 2; t2++) {
                    const __nv_bfloat16* src = (t2 ? bsrc0 : asrc0) + koff;
#pragma unroll
                    for (int it = 0; it < 4; it++) {
                        int c = tid + 256 * it;
                        int r = c >> 3, ch = c & 7;
                        cp_async16(sb + t2 * TILE_B + SW128(r * 128 + ch * 16),
                                   src + (size_t)r * D + ch * 8);
                    }
                }
                cp_commit();
                cp_wait<1>();
            } else {
                cp_wait<0>();
            }
            __syncthreads();

            uint32_t stg = sbase + s * STAGE_B;

            // double-buffered fragments
            uint32_t afr[2][2][4];
            uint32_t bfr[2][4][4];

            // load step 0 into buffer 0
            {
                int kc = lm_c;
#pragma unroll
                for (int mi = 0; mi < 2; mi++) {
                    int r = warp_m * 32 + mi * 16 + lm_r;
                    ldsm4(afr[0][mi][0], afr[0][mi][1], afr[0][mi][2],
                          afr[0][mi][3], stg + SW128(r * 128 + kc));
                }
#pragma unroll
                for (int nb = 0; nb < 4; nb++) {
                    int r = warp_n * 64 + nb * 16 + lm_r;
                    ldsm4(bfr[0][nb][0], bfr[0][nb][1], bfr[0][nb][2],
                          bfr[0][nb][3], stg + TILE_B + SW128(r * 128 + kc));
                }
            }

#pragma unroll
            for (int step = 0; step < 4; step++) {
                int cur = step & 1;
                if (step < 3) {
                    int nxt = cur ^ 1;
                    int kc = (step + 1) * 32 + lm_c;
#pragma unroll
                    for (int mi = 0; mi < 2; mi++) {
                        int r = warp_m * 32 + mi * 16 + lm_r;
                        ldsm4(afr[nxt][mi][0], afr[nxt][mi][1], afr[nxt][mi][2],
                              afr[nxt][mi][3], stg + SW128(r * 128 + kc));
                    }
#pragma unroll
                    for (int nb = 0; nb < 4; nb++) {
                        int r = warp_n * 64 + nb * 16 + lm_r;
                        ldsm4(bfr[nxt][nb][0], bfr[nxt][nb][1], bfr[nxt][nb][2],
                              bfr[nxt][nb][3],
                              stg + TILE_B + SW128(r * 128 + kc));
                    }
                }
#pragma unroll
                for (int mi = 0; mi < 2; mi++) {
#pragma unroll
                    for (int nb = 0; nb < 4; nb++) {
                        uint32_t b0[2] = { bfr[cur][nb][0], bfr[cur][nb][2] };
                        uint32_t b1[2] = { bfr[cur][nb][1], bfr[cur][nb][3] };
                        mma16816(acc[mi][nb * 2 + 0], afr[cur][mi], b0);
                        mma16816(acc[mi][nb * 2 + 1], afr[cur][mi], b1);
                    }
                }
            }
            __syncthreads();   // all warps done with stage s before overwrite
        }

        // ---- epilogue: running max + candidate insert
#pragma unroll
        for (int i = 0; i < 2; i++) {
#pragma unroll
            for (int kk = 0; kk < 2; kk++) {
                int lrow = warp_m * 32 + i * 16 + kk * 8 + g;
                float m = -INFINITY;
#pragma unroll
                for (int j = 0; j < 8; j++) {
                    m = fmaxf(m, acc[i][j][kk * 2 + 0]);
                    m = fmaxf(m, acc[i][j][kk * 2 + 1]);
                }
                atomicMax(&srowmax[lrow], fenc(m));
            }
        }
        __syncthreads();
#pragma unroll
        for (int i = 0; i < 2; i++) {
#pragma unroll
            for (int kk = 0; kk < 2; kk++) {
                int lrow = warp_m * 32 + i * 16 + kk * 8 + g;
                float thr = fdec(srowmax[lrow]) - MARGIN;
                float m = -INFINITY;
#pragma unroll
                for (int j = 0; j < 8; j++) {
                    m = fmaxf(m, acc[i][j][kk * 2 + 0]);
                    m = fmaxf(m, acc[i][j][kk * 2 + 1]);
                }
                if (m < thr) continue;
#pragma unroll
                for (int j = 0; j < 8; j++) {
#pragma unroll
                    for (int h = 0; h < 2; h++) {
                        float v = acc[i][j][kk * 2 + h];
                        if (v >= thr) {
                            int col = nt * 128 + warp_n * 64 + j * 8 + tig * 2 + h;
                            int grow = row0 + lrow;
                            int p = atomicAdd(&g_ccnt[grow], 1);
                            if (p < CAP) g_cand[(size_t)grow * CAP + p] = col;
                        }
                    }
                }
            }
        }
        // next iteration's top-of-loop __syncthreads orders srowmax reuse
    }
}

// -------------------- fused exact rescore + scatter (one block per row) -----
// Loads z row once; 8 warps rescore candidates exactly in fp32; block-reduce
// argmax; then z_q/loss/EMA-stat scatter in the same block.
__global__ __launch_bounds__(256)
void k_finish(const float* __restrict__ z,
              const float* __restrict__ cb,
              float* __restrict__ out) {
    __shared__ float4 zs[256];         // the z row
    __shared__ float red[256];
    __shared__ float wval[8];
    __shared__ int   widx[8];
    __shared__ int   s_id;

    int b = blockIdx.x;
    int t = threadIdx.x;
    int lane = t & 31;
    int w = t >> 5;

    float4 zv = ((const float4*)(z + (size_t)b * D))[t];
    zs[t] = zv;
    __syncthreads();

    int cnt = g_ccnt[b];
    if (cnt > CAP) cnt = CAP;

    // each warp rescorses candidates w, w+8, w+16, ...
    float bv = -INFINITY;
    int   bi = 0x7fffffff;
    for (int c = w; c < cnt; c += 8) {
        int idx = g_cand[(size_t)b * CAP + c];
        const float4* cp = (const float4*)(g_cbn + (size_t)idx * D);
        float s = 0.0f;
#pragma unroll
        for (int i = 0; i < 8; i++) {
            float4 zr = zs[i * 32 + lane];
            float4 cv = cp[i * 32 + lane];
            s += zr.x * cv.x + zr.y * cv.y + zr.z * cv.z + zr.w * cv.w;
        }
#pragma unroll
        for (int o = 16; o > 0; o >>= 1) s += __shfl_xor_sync(0xFFFFFFFFu, s, o);
        if (s > bv || (s == bv && idx < bi)) { bv = s; bi = idx; }
    }
    if (lane == 0) { wval[w] = bv; widx[w] = bi; }
    __syncthreads();
    if (t == 0) {
        float fv = wval[0]; int fi = widx[0];
#pragma unroll
        for (int i = 1; i < 8; i++) {
            if (wval[i] > fv || (wval[i] == fv && widx[i] < fi)) {
                fv = wval[i]; fi = widx[i];
            }
        }
        s_id = fi;
        out[OFF_IDS + b] = (float)fi;
    }
    __syncthreads();
    int id = s_id;

    // ---- scatter: z_q, loss, EMA stats
    float4 qv = ((const float4*)(cb + (size_t)id * D))[t];
    float4 zq;
    zq.x = zv.x + (qv.x - zv.x);
    zq.y = zv.y + (qv.y - zv.y);
    zq.z = zv.z + (qv.z - zv.z);
    zq.w = zv.w + (qv.w - zv.w);
    ((float4*)(out + OFF_ZQ + (size_t)b * D))[t] = zq;

    float dx = zv.x - qv.x, dy = zv.y - qv.y, dz = zv.z - qv.z, dw = zv.w - qv.w;
    red[t] = dx * dx + dy * dy + dz * dz + dw * dw;

    float* wrow = g_wsum + (size_t)id * D + t * 4;
    atomicAdd(wrow + 0, zv.x);
    atomicAdd(wrow + 1, zv.y);
    atomicAdd(wrow + 2, zv.z);
    atomicAdd(wrow + 3, zv.w);

    __syncthreads();
    for (int s = 128; s > 0; s >>= 1) {
        if (t < s) red[t] += red[t + s];
        __syncthreads();
    }
    if (t == 0) {
        atomicAdd(&g_loss, red[0]);
        atomicAdd(&g_cnt[id], 1.0f);
    }
}

// -------------------- epilogue kernels --------------------------------------
__global__ void k_count(const float* __restrict__ ema_count,
                        float* __restrict__ out) {
    int k = blockIdx.x * blockDim.x + threadIdx.x;
    if (k < K) {
        float nc = DECAY * ema_count[k] + ONE_M_D * g_cnt[k];
        g_ncnt[k] = nc;
        out[OFF_CNT + k] = nc;
    }
}

__global__ void k_final(const float* __restrict__ ema_weight,
                        float* __restrict__ out) {
    int64_t i4 = (int64_t)blockIdx.x * blockDim.x + threadIdx.x;
    if (i4 >= (int64_t)K * D / 4) return;
    int row = (int)(i4 >> 8);
    float4 ew = ((const float4*)ema_weight)[i4];
    float4 ws = ((const float4*)g_wsum)[i4];
    float w0 = DECAY * ew.x + ONE_M_D * ws.x;
    float w1 = DECAY * ew.y + ONE_M_D * ws.y;
    float w2 = DECAY * ew.z + ONE_M_D * ws.z;
    float w3 = DECAY * ew.w + ONE_M_D * ws.w;
    int64_t base = i4 * 4;
    out[OFF_W + base + 0] = w0;
    out[OFF_W + base + 1] = w1;
    out[OFF_W + base + 2] = w2;
    out[OFF_W + base + 3] = w3;
    float denom = g_ncnt[row] + EPS;
    out[OFF_CB + base + 0] = w0 / denom;
    out[OFF_CB + base + 1] = w1 / denom;
    out[OFF_CB + base + 2] = w2 / denom;
    out[OFF_CB + base + 3] = w3 / denom;
}

__global__ void k_loss(float* __restrict__ out) {
    out[OFF_LOSS] = COMMIT * (g_loss / (float)((int64_t)B * D));
}

// ---------------------------------------------------------------------------
extern "C" void kernel_launch(void* const* d_in, const int* in_sizes, int n_in,
                              void* d_out, int out_size) {
    const float* z          = (const float*)d_in[0];
    const float* codebook   = (const float*)d_in[1];
    const float* ema_count  = (const float*)d_in[2];
    const float* ema_weight = (const float*)d_in[3];
    float* out = (float*)d_out;

    cudaFuncSetAttribute(k_approx, cudaFuncAttributeMaxDynamicSharedMemorySize,
                         DYN_SMEM);

    k_zero<<<2048, 256>>>();
    k_cast_z<<<4096, 256>>>(z);
    k_norm_cb<<<K, 256>>>(codebook);
    k_approx<<<B / 128, 256, DYN_SMEM>>>(0);
    k_finish<<<B, 256>>>(z, codebook, out);
    k_count<<<(K + 255) / 256, 256>>>(ema_count, out);
    k_final<<<(K * D / 4 + 255) / 256, 256>>>(ema_weight, out);
    k_loss<<<1, 1>>>(out);
}